// round 6
// baseline (speedup 1.0000x reference)
#include <cuda_runtime.h>
#include <cuda_bf16.h>
#include <cstdint>

#define Bc 8
#define Gc 256
#define Nn 1024
#define Pc 4
#define Fc 256
#define Kc 4
#define NBP 32

// ======================= device scratch ======================================
__device__ float g_e1[NBP * Nn];
__device__ float g_e2[NBP * Nn];
__device__ __nv_bfloat16 g_ah[(size_t)NBP * Nn * Nn];   // aij hi, row-major [j][n]
__device__ __nv_bfloat16 g_al[(size_t)NBP * Nn * Nn];   // aij lo
__device__ __nv_bfloat16 g_zsh[(size_t)NBP * Nn * Nn];  // z stacked [k*G+g][n] hi
__device__ __nv_bfloat16 g_zsl[(size_t)NBP * Nn * Nn];  // lo
__device__ __nv_bfloat16 g_fwh[(size_t)Pc * Fc * Kc * Gc];
__device__ __nv_bfloat16 g_fwl[(size_t)Pc * Fc * Kc * Gc];

__device__ __forceinline__ void split2(float v, __nv_bfloat16& h, __nv_bfloat16& l) {
    h = __float2bfloat16(v);
    l = __float2bfloat16(v - __bfloat162float(h));
}

// ======================= helpers =============================================
__device__ __forceinline__ uint32_t smem_u32(const void* p) {
    uint32_t a;
    asm("{ .reg .u64 t; cvta.to.shared.u64 t, %1; cvt.u32.u64 %0, t; }" : "=r"(a) : "l"(p));
    return a;
}
__device__ __forceinline__ void cpa16(uint32_t dst, const void* src) {
    asm volatile("cp.async.cg.shared.global [%0], [%1], 16;" :: "r"(dst), "l"(src));
}
__device__ __forceinline__ void cpa_commit() { asm volatile("cp.async.commit_group;" ::: "memory"); }

#define SWZ(off) ((off) ^ (((off) >> 3) & 0x70))

__device__ __forceinline__ void ldm_x4(uint32_t& r0, uint32_t& r1, uint32_t& r2, uint32_t& r3,
                                       uint32_t addr) {
    asm volatile("ldmatrix.sync.aligned.m8n8.x4.shared.b16 {%0,%1,%2,%3}, [%4];"
                 : "=r"(r0), "=r"(r1), "=r"(r2), "=r"(r3) : "r"(addr));
}
__device__ __forceinline__ void ldm_x4t(uint32_t& r0, uint32_t& r1, uint32_t& r2, uint32_t& r3,
                                        uint32_t addr) {
    asm volatile("ldmatrix.sync.aligned.m8n8.x4.trans.shared.b16 {%0,%1,%2,%3}, [%4];"
                 : "=r"(r0), "=r"(r1), "=r"(r2), "=r"(r3) : "r"(addr));
}
__device__ __forceinline__ void mma16816(float* c, const uint32_t* a, const uint32_t* b) {
    asm volatile(
        "mma.sync.aligned.m16n8k16.row.col.f32.bf16.bf16.f32 "
        "{%0,%1,%2,%3}, {%4,%5,%6,%7}, {%8,%9}, {%0,%1,%2,%3};"
        : "+f"(c[0]), "+f"(c[1]), "+f"(c[2]), "+f"(c[3])
        : "r"(a[0]), "r"(a[1]), "r"(a[2]), "r"(a[3]), "r"(b[0]), "r"(b[1]));
}

// ======================= fused input split (x -> zs slice0, fw -> hi/lo) ======
__global__ void split_kernel(const float* __restrict__ x, const float* __restrict__ fw) {
    int t = blockIdx.x * blockDim.x + threadIdx.x;
    const int XT = Bc * Gc * Nn;          // 2M
    const int FT = Pc * Fc * Kc * Gc;     // 1M
    if (t < XT) {
        int n = t & (Nn - 1);
        int g = (t >> 10) & (Gc - 1);
        int b = t >> 18;
        __nv_bfloat16 h, l;
        split2(x[t], h, l);
#pragma unroll
        for (int p = 0; p < 4; ++p) {
            size_t o = ((size_t)(b * 4 + p) * Nn + g) * Nn + n;
            g_zsh[o] = h;
            g_zsl[o] = l;
        }
    } else {
        int i = t - XT;
        if (i < FT) {
            __nv_bfloat16 h, l;
            split2(fw[i], h, l);
            g_fwh[i] = h;
            g_fwl[i] = l;
        }
    }
}

// ======================= fused prep + e: e1/e2[bp][n] =========================
__global__ void pe_kernel(const float* __restrict__ x,
                          const float* __restrict__ mixer,
                          const float* __restrict__ weight,
                          const float* __restrict__ wb) {
    int bp = blockIdx.y;
    int b = bp >> 2, p = bp & 3;
    int tid = threadIdx.x;
    __shared__ float s1[Gc], s2[Gc], sc[2];
    {
        int g = tid;
        float v1 = 0.f, v2 = 0.f;
        const float* mw1 = mixer + p * 2 * Fc;
        const float* mw2 = mw1 + Fc;
#pragma unroll 8
        for (int f = 0; f < Fc; ++f) {
            float w = weight[((size_t)(p * Fc + f)) * Gc + g];
            v1 = fmaf(mw1[f], w, v1);
            v2 = fmaf(mw2[f], w, v2);
        }
        s1[g] = v1;
        s2[g] = v2;
        if (g == 0) {
            float c1 = 0.f, c2 = 0.f;
            for (int f = 0; f < Fc; ++f) {
                c1 = fmaf(mw1[f], wb[p * Fc + f], c1);
                c2 = fmaf(mw2[f], wb[p * Fc + f], c2);
            }
            sc[0] = c1;
            sc[1] = c2;
        }
    }
    __syncthreads();
    int n = blockIdx.x * blockDim.x + tid;
    const float* xb = x + (size_t)b * Gc * Nn + n;
    float a1 = 0.f, a2 = 0.f;
#pragma unroll 8
    for (int g = 0; g < Gc; ++g) {
        float xv = xb[(size_t)g * Nn];
        a1 = fmaf(s1[g], xv, a1);
        a2 = fmaf(s2[g], xv, a2);
    }
    g_e1[bp * Nn + n] = a1 + sc[0];
    g_e2[bp * Nn + n] = a2 + sc[1];
}

// ======================= reductions ==========================================
__device__ __forceinline__ float blockReduceMax(float v, float* sm) {
#pragma unroll
    for (int o = 16; o; o >>= 1) v = fmaxf(v, __shfl_xor_sync(0xffffffffu, v, o));
    if ((threadIdx.x & 31) == 0) sm[threadIdx.x >> 5] = v;
    __syncthreads();
    if (threadIdx.x < 32) {
        float t = (threadIdx.x < 8) ? sm[threadIdx.x] : -3.0e38f;
#pragma unroll
        for (int o = 4; o; o >>= 1) t = fmaxf(t, __shfl_xor_sync(0xffffffffu, t, o));
        if (threadIdx.x == 0) sm[0] = t;
    }
    __syncthreads();
    float r = sm[0];
    __syncthreads();
    return r;
}
__device__ __forceinline__ float blockReduceSum(float v, float* sm) {
#pragma unroll
    for (int o = 16; o; o >>= 1) v += __shfl_xor_sync(0xffffffffu, v, o);
    if ((threadIdx.x & 31) == 0) sm[threadIdx.x >> 5] = v;
    __syncthreads();
    if (threadIdx.x < 32) {
        float t = (threadIdx.x < 8) ? sm[threadIdx.x] : 0.f;
#pragma unroll
        for (int o = 4; o; o >>= 1) t += __shfl_xor_sync(0xffffffffu, t, o);
        if (threadIdx.x == 0) sm[0] = t;
    }
    __syncthreads();
    float r = sm[0];
    __syncthreads();
    return r;
}

// ======================= softmax rows -> aij hi/lo row-major ==================
__global__ void aij_kernel(const float* __restrict__ S) {
    int i = blockIdx.x, bp = blockIdx.y, b = bp >> 2;
    __shared__ float sm[8];
    float e2i = g_e2[bp * Nn + i];
    const float* e1r = g_e1 + bp * Nn;
    const float* Sr = S + (size_t)b * Nn * Nn + (size_t)i * Nn;
    float lv[4];
    int mk[4];
    float vmax = -3.0e38f;
#pragma unroll
    for (int q = 0; q < 4; ++q) {
        int j = threadIdx.x + q * 256;
        float s = Sr[j];
        int m = (fabsf(s) > 1e-9f);
        float e = e1r[j] + e2i;
        float l = e > 0.f ? e : 0.2f * e;
        lv[q] = l;
        mk[q] = m;
        if (m) vmax = fmaxf(vmax, l);
    }
    vmax = blockReduceMax(vmax, sm);
    float pv[4];
    float sum = 0.f;
#pragma unroll
    for (int q = 0; q < 4; ++q) {
        float pe = mk[q] ? __expf(lv[q] - vmax) : 0.f;
        pv[q] = pe;
        sum += pe;
    }
    sum = blockReduceSum(sum, sm);
    float inv = 1.f / sum;
    size_t rowo = (size_t)bp * Nn * Nn + (size_t)i * Nn;
#pragma unroll
    for (int q = 0; q < 4; ++q) {
        int j = threadIdx.x + q * 256;
        __nv_bfloat16 h, l;
        split2(pv[q] * inv, h, l);
        g_ah[rowo + j] = h;
        g_al[rowo + j] = l;
    }
}

// ======================= HMMA GEMM ============================================
// CTA tile 128(m) x 256(n), K=1024, BK=32, 3-stage cp.async pipeline.
// MMA schedule: per (s, ng) six sweeps over mt so accumulator reuse is 8
// independent HMMAs apart (no back-to-back RAW on the tensor pipe).
#define TBK 32
#define NCH (Nn / TBK)
#define ASTG 16384
#define BSTG 32768
#define STG (ASTG + BSTG)
#define NSTAGE 3
#define SMEM_GEMM (NSTAGE * STG)

__device__ __forceinline__ void cpa_wait2() { asm volatile("cp.async.wait_group 2;" ::: "memory"); }
__device__ __forceinline__ void cpa_wait1() { asm volatile("cp.async.wait_group 1;" ::: "memory"); }
__device__ __forceinline__ void cpa_wait0() { asm volatile("cp.async.wait_group 0;" ::: "memory"); }

__global__ void __launch_bounds__(256, 1)
mma_gemm(const float* __restrict__ bias, float* __restrict__ out, int mode, int kstep) {
    extern __shared__ __align__(1024) char smem[];
    uint32_t sb = smem_u32(smem);
    const int bp = blockIdx.z, p = bp & 3;
    const int m0 = blockIdx.y * 128, n0 = blockIdx.x * 256;
    const int tid = threadIdx.x, wid = tid >> 5, lane = tid & 31;
    const int warp_m = wid >> 2, warp_n = wid & 3;  // 2 x 4 warps, warp tile 64x64
    const size_t NN = (size_t)Nn * Nn;

    const __nv_bfloat16 *Ah, *Al, *Bh, *Bl;
    if (mode == 0) {
        Ah = g_zsh + ((size_t)bp * Nn + (size_t)(kstep - 1) * Gc) * Nn;
        Al = g_zsl + ((size_t)bp * Nn + (size_t)(kstep - 1) * Gc) * Nn;
        Bh = g_ah + (size_t)bp * NN;
        Bl = g_al + (size_t)bp * NN;
    } else {
        Ah = g_fwh + (size_t)p * Fc * Nn;
        Al = g_fwl + (size_t)p * Fc * Nn;
        Bh = g_zsh + (size_t)bp * NN;
        Bl = g_zsl + (size_t)bp * NN;
    }

    float acc[4][8][4];
#pragma unroll
    for (int i = 0; i < 4; ++i)
#pragma unroll
        for (int j = 0; j < 8; ++j)
#pragma unroll
            for (int q = 0; q < 4; ++q) acc[i][j][q] = 0.f;

    auto load_stage = [&](int c, int s) {
        uint32_t base = sb + s * STG;
        int k0 = c * TBK;
#pragma unroll
        for (int i = 0; i < 4; ++i) {
            int idx = i * 256 + tid;
            int r = idx >> 3, ch = idx & 7;
            const __nv_bfloat16* src = ((ch < 4) ? Ah : Al) + (size_t)(m0 + r) * Nn + k0 + (ch & 3) * 8;
            cpa16(base + SWZ(r * 128 + ch * 16), src);
        }
#pragma unroll
        for (int i = 0; i < 8; ++i) {
            int idx = i * 256 + tid;
            int r = idx >> 6, c = idx & 63;
            int half = c >> 5, c5 = c & 31;
            const __nv_bfloat16* src = (half ? Bl : Bh) + (size_t)(k0 + r) * Nn + n0 + c5 * 8;
            cpa16(base + ASTG + r * 1024 + half * 512 + ((c5 ^ (r & 7)) * 16), src);
        }
        cpa_commit();
    };

    const int a_row = (lane & 7) + ((lane >> 3) & 1) * 8;
    const int a_k16 = lane >> 4;
    const int b_krow = lane & 15;
    const int b_nsel = lane >> 4;

    load_stage(0, 0);
    load_stage(1, 1);
    for (int c = 0; c < NCH; ++c) {
        if (c + 2 < NCH) {
            load_stage(c + 2, (c + 2) % NSTAGE);
            cpa_wait2();
        } else if (c + 1 < NCH) {
            cpa_wait1();
        } else {
            cpa_wait0();
        }
        __syncthreads();
        uint32_t Abase = sb + (c % NSTAGE) * STG;
        uint32_t Bbase = Abase + ASTG;
#pragma unroll
        for (int s = 0; s < 2; ++s) {
            uint32_t ah[4][4], al[4][4];
#pragma unroll
            for (int mt = 0; mt < 4; ++mt) {
                int row = warp_m * 64 + mt * 16 + a_row;
                int chh = s * 2 + a_k16;
                ldm_x4(ah[mt][0], ah[mt][1], ah[mt][2], ah[mt][3],
                       Abase + SWZ(row * 128 + chh * 16));
                ldm_x4(al[mt][0], al[mt][1], al[mt][2], al[mt][3],
                       Abase + SWZ(row * 128 + 64 + chh * 16));
            }
#pragma unroll
            for (int ng = 0; ng < 4; ++ng) {
                int k = s * 16 + b_krow;
                int c5 = (warp_n * 64 + ng * 16) / 8 + b_nsel;
                uint32_t addr = Bbase + k * 1024 + ((c5 ^ (k & 7)) * 16);
                uint32_t bh[4], bl[4];
                ldm_x4t(bh[0], bh[1], bh[2], bh[3], addr);
                ldm_x4t(bl[0], bl[1], bl[2], bl[3], addr + 512);
                // six sweeps over mt: accumulator reuse spaced 8 MMAs apart
#pragma unroll
                for (int mt = 0; mt < 4; ++mt) mma16816(acc[mt][2 * ng],     ah[mt], &bh[0]);
#pragma unroll
                for (int mt = 0; mt < 4; ++mt) mma16816(acc[mt][2 * ng + 1], ah[mt], &bh[2]);
#pragma unroll
                for (int mt = 0; mt < 4; ++mt) mma16816(acc[mt][2 * ng],     ah[mt], &bl[0]);
#pragma unroll
                for (int mt = 0; mt < 4; ++mt) mma16816(acc[mt][2 * ng + 1], ah[mt], &bl[2]);
#pragma unroll
                for (int mt = 0; mt < 4; ++mt) mma16816(acc[mt][2 * ng],     al[mt], &bh[0]);
#pragma unroll
                for (int mt = 0; mt < 4; ++mt) mma16816(acc[mt][2 * ng + 1], al[mt], &bh[2]);
            }
        }
        __syncthreads();
    }

    // ---------------- epilogue ----------------
    const int r_base = m0 + warp_m * 64 + (lane >> 2);
    const int c_base = n0 + warp_n * 64 + (lane & 3) * 2;
    if (mode == 0) {
        __nv_bfloat16* Zh = g_zsh + ((size_t)bp * Nn + (size_t)kstep * Gc) * Nn;
        __nv_bfloat16* Zl = g_zsl + ((size_t)bp * Nn + (size_t)kstep * Gc) * Nn;
#pragma unroll
        for (int mt = 0; mt < 4; ++mt)
#pragma unroll
            for (int nt = 0; nt < 8; ++nt) {
#pragma unroll
                for (int h = 0; h < 2; ++h) {
                    int r = r_base + mt * 16 + h * 8;
                    int cc = c_base + nt * 8;
                    float v0 = acc[mt][nt][2 * h], v1 = acc[mt][nt][2 * h + 1];
                    __nv_bfloat16 h0, l0, h1, l1;
                    split2(v0, h0, l0);
                    split2(v1, h1, l1);
                    __nv_bfloat162 ph, pl;
                    ph.x = h0; ph.y = h1;
                    pl.x = l0; pl.y = l1;
                    *(__nv_bfloat162*)(Zh + (size_t)r * Nn + cc) = ph;
                    *(__nv_bfloat162*)(Zl + (size_t)r * Nn + cc) = pl;
                }
            }
    } else {
        float* C = out + (size_t)bp * Fc * Nn;
#pragma unroll
        for (int mt = 0; mt < 4; ++mt)
#pragma unroll
            for (int nt = 0; nt < 8; ++nt) {
#pragma unroll
                for (int h = 0; h < 2; ++h) {
                    int r = r_base + mt * 16 + h * 8;
                    int cc = c_base + nt * 8;
                    float bv = bias[r];
                    float t0 = acc[mt][nt][2 * h] + bv;
                    float t1 = acc[mt][nt][2 * h + 1] + bv;
                    t0 = t0 > 0.f ? t0 : 0.01f * t0;
                    t1 = t1 > 0.f ? t1 : 0.01f * t1;
                    *(float2*)(C + (size_t)r * Nn + cc) = make_float2(t0, t1);
                }
            }
    }
}

// ======================= launch ================================================
extern "C" void kernel_launch(void* const* d_in, const int* in_sizes, int n_in,
                              void* d_out, int out_size) {
    const float* x      = (const float*)d_in[0];
    const float* mixer  = (const float*)d_in[1];
    const float* weight = (const float*)d_in[2];
    const float* wb     = (const float*)d_in[3];
    const float* fw     = (const float*)d_in[4];
    const float* bias   = (const float*)d_in[5];
    const float* S      = (const float*)d_in[6];
    float* out = (float*)d_out;

    cudaFuncSetAttribute(mma_gemm, cudaFuncAttributeMaxDynamicSharedMemorySize, SMEM_GEMM);

    const int XT = Bc * Gc * Nn, FT = Pc * Fc * Kc * Gc;
    split_kernel<<<(XT + FT + 255) / 256, 256>>>(x, fw);        // 1
    pe_kernel<<<dim3(Nn / 256, NBP), 256>>>(x, mixer, weight, wb);  // 2
    aij_kernel<<<dim3(Nn, NBP), 256>>>(S);                      // 3

    dim3 gg(Nn / 256, 2, NBP);
    for (int k = 1; k < Kc; ++k)                                // 4,5,6  (#4 = GEMM profile)
        mma_gemm<<<gg, 256, SMEM_GEMM>>>(bias, out, 0, k);
    mma_gemm<<<gg, 256, SMEM_GEMM>>>(bias, out, 1, 0);          // 7
}

// round 7
// speedup vs baseline: 1.0281x; 1.0281x over previous
#include <cuda_runtime.h>
#include <cuda_bf16.h>
#include <cstdint>

#define Bc 8
#define Gc 256
#define Nn 1024
#define Pc 4
#define Fc 256
#define Kc 4
#define NBP 32

// ======================= device scratch ======================================
__device__ float g_e1[NBP * Nn];
__device__ float g_e2[NBP * Nn];
__device__ __nv_bfloat16 g_ah[(size_t)NBP * Nn * Nn];   // aij hi, row-major [j][n]
__device__ __nv_bfloat16 g_al[(size_t)NBP * Nn * Nn];   // aij lo
__device__ __nv_bfloat16 g_zsh[(size_t)NBP * Nn * Nn];  // z stacked [k*G+g][n] hi
__device__ __nv_bfloat16 g_zsl[(size_t)NBP * Nn * Nn];  // lo
__device__ __nv_bfloat16 g_fwh[(size_t)Pc * Fc * Kc * Gc];
__device__ __nv_bfloat16 g_fwl[(size_t)Pc * Fc * Kc * Gc];

__device__ __forceinline__ void split2(float v, __nv_bfloat16& h, __nv_bfloat16& l) {
    h = __float2bfloat16(v);
    l = __float2bfloat16(v - __bfloat162float(h));
}

// ======================= helpers =============================================
__device__ __forceinline__ uint32_t smem_u32(const void* p) {
    uint32_t a;
    asm("{ .reg .u64 t; cvta.to.shared.u64 t, %1; cvt.u32.u64 %0, t; }" : "=r"(a) : "l"(p));
    return a;
}
__device__ __forceinline__ void cpa16(uint32_t dst, const void* src) {
    asm volatile("cp.async.cg.shared.global [%0], [%1], 16;" :: "r"(dst), "l"(src));
}
__device__ __forceinline__ void cpa_commit() { asm volatile("cp.async.commit_group;" ::: "memory"); }

#define SWZ(off) ((off) ^ (((off) >> 3) & 0x70))

__device__ __forceinline__ void ldm_x4(uint32_t& r0, uint32_t& r1, uint32_t& r2, uint32_t& r3,
                                       uint32_t addr) {
    asm volatile("ldmatrix.sync.aligned.m8n8.x4.shared.b16 {%0,%1,%2,%3}, [%4];"
                 : "=r"(r0), "=r"(r1), "=r"(r2), "=r"(r3) : "r"(addr));
}
__device__ __forceinline__ void ldm_x4t(uint32_t& r0, uint32_t& r1, uint32_t& r2, uint32_t& r3,
                                        uint32_t addr) {
    asm volatile("ldmatrix.sync.aligned.m8n8.x4.trans.shared.b16 {%0,%1,%2,%3}, [%4];"
                 : "=r"(r0), "=r"(r1), "=r"(r2), "=r"(r3) : "r"(addr));
}
__device__ __forceinline__ void mma16816(float* c, const uint32_t* a, const uint32_t* b) {
    asm volatile(
        "mma.sync.aligned.m16n8k16.row.col.f32.bf16.bf16.f32 "
        "{%0,%1,%2,%3}, {%4,%5,%6,%7}, {%8,%9}, {%0,%1,%2,%3};"
        : "+f"(c[0]), "+f"(c[1]), "+f"(c[2]), "+f"(c[3])
        : "r"(a[0]), "r"(a[1]), "r"(a[2]), "r"(a[3]), "r"(b[0]), "r"(b[1]));
}

// ======================= fused input split (x -> zs slice0, fw -> hi/lo) ======
__global__ void split_kernel(const float* __restrict__ x, const float* __restrict__ fw) {
    int t = blockIdx.x * blockDim.x + threadIdx.x;
    const int XT = Bc * Gc * Nn;
    const int FT = Pc * Fc * Kc * Gc;
    if (t < XT) {
        int n = t & (Nn - 1);
        int g = (t >> 10) & (Gc - 1);
        int b = t >> 18;
        __nv_bfloat16 h, l;
        split2(x[t], h, l);
#pragma unroll
        for (int p = 0; p < 4; ++p) {
            size_t o = ((size_t)(b * 4 + p) * Nn + g) * Nn + n;
            g_zsh[o] = h;
            g_zsl[o] = l;
        }
    } else {
        int i = t - XT;
        if (i < FT) {
            __nv_bfloat16 h, l;
            split2(fw[i], h, l);
            g_fwh[i] = h;
            g_fwl[i] = l;
        }
    }
}

// ======================= fused prep + e: e1/e2[bp][n] =========================
__global__ void pe_kernel(const float* __restrict__ x,
                          const float* __restrict__ mixer,
                          const float* __restrict__ weight,
                          const float* __restrict__ wb) {
    int bp = blockIdx.y;
    int b = bp >> 2, p = bp & 3;
    int tid = threadIdx.x;
    __shared__ float s1[Gc], s2[Gc], sc[2];
    {
        int g = tid;
        float v1 = 0.f, v2 = 0.f;
        const float* mw1 = mixer + p * 2 * Fc;
        const float* mw2 = mw1 + Fc;
#pragma unroll 8
        for (int f = 0; f < Fc; ++f) {
            float w = weight[((size_t)(p * Fc + f)) * Gc + g];
            v1 = fmaf(mw1[f], w, v1);
            v2 = fmaf(mw2[f], w, v2);
        }
        s1[g] = v1;
        s2[g] = v2;
        if (g == 0) {
            float c1 = 0.f, c2 = 0.f;
            for (int f = 0; f < Fc; ++f) {
                c1 = fmaf(mw1[f], wb[p * Fc + f], c1);
                c2 = fmaf(mw2[f], wb[p * Fc + f], c2);
            }
            sc[0] = c1;
            sc[1] = c2;
        }
    }
    __syncthreads();
    int n = blockIdx.x * blockDim.x + tid;
    const float* xb = x + (size_t)b * Gc * Nn + n;
    float a1 = 0.f, a2 = 0.f;
#pragma unroll 8
    for (int g = 0; g < Gc; ++g) {
        float xv = xb[(size_t)g * Nn];
        a1 = fmaf(s1[g], xv, a1);
        a2 = fmaf(s2[g], xv, a2);
    }
    g_e1[bp * Nn + n] = a1 + sc[0];
    g_e2[bp * Nn + n] = a2 + sc[1];
}

// ======================= reductions ==========================================
__device__ __forceinline__ float blockReduceMax(float v, float* sm) {
#pragma unroll
    for (int o = 16; o; o >>= 1) v = fmaxf(v, __shfl_xor_sync(0xffffffffu, v, o));
    if ((threadIdx.x & 31) == 0) sm[threadIdx.x >> 5] = v;
    __syncthreads();
    if (threadIdx.x < 32) {
        float t = (threadIdx.x < 8) ? sm[threadIdx.x] : -3.0e38f;
#pragma unroll
        for (int o = 4; o; o >>= 1) t = fmaxf(t, __shfl_xor_sync(0xffffffffu, t, o));
        if (threadIdx.x == 0) sm[0] = t;
    }
    __syncthreads();
    float r = sm[0];
    __syncthreads();
    return r;
}
__device__ __forceinline__ float blockReduceSum(float v, float* sm) {
#pragma unroll
    for (int o = 16; o; o >>= 1) v += __shfl_xor_sync(0xffffffffu, v, o);
    if ((threadIdx.x & 31) == 0) sm[threadIdx.x >> 5] = v;
    __syncthreads();
    if (threadIdx.x < 32) {
        float t = (threadIdx.x < 8) ? sm[threadIdx.x] : 0.f;
#pragma unroll
        for (int o = 4; o; o >>= 1) t += __shfl_xor_sync(0xffffffffu, t, o);
        if (threadIdx.x == 0) sm[0] = t;
    }
    __syncthreads();
    float r = sm[0];
    __syncthreads();
    return r;
}

// ======================= softmax rows -> aij hi/lo row-major ==================
__global__ void aij_kernel(const float* __restrict__ S) {
    int i = blockIdx.x, bp = blockIdx.y, b = bp >> 2;
    __shared__ float sm[8];
    float e2i = g_e2[bp * Nn + i];
    const float* e1r = g_e1 + bp * Nn;
    const float* Sr = S + (size_t)b * Nn * Nn + (size_t)i * Nn;
    float lv[4];
    int mk[4];
    float vmax = -3.0e38f;
#pragma unroll
    for (int q = 0; q < 4; ++q) {
        int j = threadIdx.x + q * 256;
        float s = Sr[j];
        int m = (fabsf(s) > 1e-9f);
        float e = e1r[j] + e2i;
        float l = e > 0.f ? e : 0.2f * e;
        lv[q] = l;
        mk[q] = m;
        if (m) vmax = fmaxf(vmax, l);
    }
    vmax = blockReduceMax(vmax, sm);
    float pv[4];
    float sum = 0.f;
#pragma unroll
    for (int q = 0; q < 4; ++q) {
        float pe = mk[q] ? __expf(lv[q] - vmax) : 0.f;
        pv[q] = pe;
        sum += pe;
    }
    sum = blockReduceSum(sum, sm);
    float inv = 1.f / sum;
    size_t rowo = (size_t)bp * Nn * Nn + (size_t)i * Nn;
#pragma unroll
    for (int q = 0; q < 4; ++q) {
        int j = threadIdx.x + q * 256;
        __nv_bfloat16 h, l;
        split2(pv[q] * inv, h, l);
        g_ah[rowo + j] = h;
        g_al[rowo + j] = l;
    }
}

// ======================= HMMA GEMM ============================================
// CTA tile 128(m) x 128(n), 8 warps (2m x 4n), warp tile 64x32, BK=32,
// 3-stage cp.async pipeline, 2 CTAs/SM (regs capped at 128).
// A smem/stage: 128 rows x 128B (64B hi | 64B lo), SWZ swizzle.
// B smem/stage: 32 k-rows x 512B (256B hi | 256B lo), chunk-XOR swizzle,
//               consumed with ldmatrix.x4.trans.
#define TBK 32
#define NCH (Nn / TBK)
#define ASTG 16384
#define BSTG 16384
#define STG (ASTG + BSTG)
#define NSTAGE 3
#define SMEM_GEMM (NSTAGE * STG)

__device__ __forceinline__ void cpa_wait2() { asm volatile("cp.async.wait_group 2;" ::: "memory"); }
__device__ __forceinline__ void cpa_wait1() { asm volatile("cp.async.wait_group 1;" ::: "memory"); }
__device__ __forceinline__ void cpa_wait0() { asm volatile("cp.async.wait_group 0;" ::: "memory"); }

__global__ void __launch_bounds__(256, 2)
mma_gemm(const float* __restrict__ bias, float* __restrict__ out, int mode, int kstep) {
    extern __shared__ __align__(1024) char smem[];
    uint32_t sb = smem_u32(smem);
    const int bp = blockIdx.z, p = bp & 3;
    const int m0 = blockIdx.y * 128, n0 = blockIdx.x * 128;
    const int tid = threadIdx.x, wid = tid >> 5, lane = tid & 31;
    const int warp_m = wid >> 2, warp_n = wid & 3;  // 2 x 4 warps, warp tile 64x32
    const size_t NN = (size_t)Nn * Nn;

    const __nv_bfloat16 *Ah, *Al, *Bh, *Bl;
    if (mode == 0) {
        Ah = g_zsh + ((size_t)bp * Nn + (size_t)(kstep - 1) * Gc) * Nn;
        Al = g_zsl + ((size_t)bp * Nn + (size_t)(kstep - 1) * Gc) * Nn;
        Bh = g_ah + (size_t)bp * NN;
        Bl = g_al + (size_t)bp * NN;
    } else {
        Ah = g_fwh + (size_t)p * Fc * Nn;
        Al = g_fwl + (size_t)p * Fc * Nn;
        Bh = g_zsh + (size_t)bp * NN;
        Bl = g_zsl + (size_t)bp * NN;
    }

    float acc[4][4][4];
#pragma unroll
    for (int i = 0; i < 4; ++i)
#pragma unroll
        for (int j = 0; j < 4; ++j)
#pragma unroll
            for (int q = 0; q < 4; ++q) acc[i][j][q] = 0.f;

    auto load_stage = [&](int c, int s) {
        uint32_t base = sb + s * STG;
        int k0 = c * TBK;
        // A: 128 rows x 8 chunks(16B) = 1024 -> 4/thread
#pragma unroll
        for (int i = 0; i < 4; ++i) {
            int idx = i * 256 + tid;
            int r = idx >> 3, ch = idx & 7;
            const __nv_bfloat16* src = ((ch < 4) ? Ah : Al) + (size_t)(m0 + r) * Nn + k0 + (ch & 3) * 8;
            cpa16(base + SWZ(r * 128 + ch * 16), src);
        }
        // B: 32 rows x 32 chunks (16 hi + 16 lo) = 1024 -> 4/thread
#pragma unroll
        for (int i = 0; i < 4; ++i) {
            int idx = i * 256 + tid;
            int r = idx >> 5, c = idx & 31;
            int half = c >> 4, c4 = c & 15;
            const __nv_bfloat16* src = (half ? Bl : Bh) + (size_t)(k0 + r) * Nn + n0 + c4 * 8;
            cpa16(base + ASTG + r * 512 + half * 256 + ((c4 ^ (r & 7)) * 16), src);
        }
        cpa_commit();
    };

    const int a_row = (lane & 7) + ((lane >> 3) & 1) * 8;
    const int a_k16 = lane >> 4;
    const int b_krow = lane & 15;
    const int b_nsel = lane >> 4;

    load_stage(0, 0);
    load_stage(1, 1);
    for (int c = 0; c < NCH; ++c) {
        if (c + 2 < NCH) {
            load_stage(c + 2, (c + 2) % NSTAGE);
            cpa_wait2();
        } else if (c + 1 < NCH) {
            cpa_wait1();
        } else {
            cpa_wait0();
        }
        __syncthreads();
        uint32_t Abase = sb + (c % NSTAGE) * STG;
        uint32_t Bbase = Abase + ASTG;
#pragma unroll
        for (int s = 0; s < 2; ++s) {
            // B fragments for this warp's 32 columns, k16 slice s
            uint32_t bh[8], bl[8];
#pragma unroll
            for (int ng = 0; ng < 2; ++ng) {
                int k = s * 16 + b_krow;
                int c4 = warp_n * 4 + ng * 2 + b_nsel;
                uint32_t addr = Bbase + k * 512 + ((c4 ^ (k & 7)) * 16);
                ldm_x4t(bh[ng * 4 + 0], bh[ng * 4 + 1], bh[ng * 4 + 2], bh[ng * 4 + 3], addr);
                ldm_x4t(bl[ng * 4 + 0], bl[ng * 4 + 1], bl[ng * 4 + 2], bl[ng * 4 + 3], addr + 256);
            }
            // A fragments in two mt-pairs to keep register pressure low
#pragma unroll
            for (int mh = 0; mh < 2; ++mh) {
                uint32_t ah[2][4], al[2][4];
#pragma unroll
                for (int q = 0; q < 2; ++q) {
                    int row = warp_m * 64 + (mh * 2 + q) * 16 + a_row;
                    int chh = s * 2 + a_k16;
                    ldm_x4(ah[q][0], ah[q][1], ah[q][2], ah[q][3],
                           Abase + SWZ(row * 128 + chh * 16));
                    ldm_x4(al[q][0], al[q][1], al[q][2], al[q][3],
                           Abase + SWZ(row * 128 + 64 + chh * 16));
                }
                // three product sweeps; acc reuse spaced 8 MMAs apart
#pragma unroll
                for (int q = 0; q < 2; ++q)
#pragma unroll
                    for (int nt = 0; nt < 4; ++nt)
                        mma16816(acc[mh * 2 + q][nt], ah[q], &bh[nt * 2]);
#pragma unroll
                for (int q = 0; q < 2; ++q)
#pragma unroll
                    for (int nt = 0; nt < 4; ++nt)
                        mma16816(acc[mh * 2 + q][nt], ah[q], &bl[nt * 2]);
#pragma unroll
                for (int q = 0; q < 2; ++q)
#pragma unroll
                    for (int nt = 0; nt < 4; ++nt)
                        mma16816(acc[mh * 2 + q][nt], al[q], &bh[nt * 2]);
            }
        }
        __syncthreads();
    }

    // ---------------- epilogue ----------------
    const int r_base = m0 + warp_m * 64 + (lane >> 2);
    const int c_base = n0 + warp_n * 32 + (lane & 3) * 2;
    if (mode == 0) {
        __nv_bfloat16* Zh = g_zsh + ((size_t)bp * Nn + (size_t)kstep * Gc) * Nn;
        __nv_bfloat16* Zl = g_zsl + ((size_t)bp * Nn + (size_t)kstep * Gc) * Nn;
#pragma unroll
        for (int mt = 0; mt < 4; ++mt)
#pragma unroll
            for (int nt = 0; nt < 4; ++nt) {
#pragma unroll
                for (int h = 0; h < 2; ++h) {
                    int r = r_base + mt * 16 + h * 8;
                    int cc = c_base + nt * 8;
                    float v0 = acc[mt][nt][2 * h], v1 = acc[mt][nt][2 * h + 1];
                    __nv_bfloat16 h0, l0, h1, l1;
                    split2(v0, h0, l0);
                    split2(v1, h1, l1);
                    __nv_bfloat162 ph, pl;
                    ph.x = h0; ph.y = h1;
                    pl.x = l0; pl.y = l1;
                    *(__nv_bfloat162*)(Zh + (size_t)r * Nn + cc) = ph;
                    *(__nv_bfloat162*)(Zl + (size_t)r * Nn + cc) = pl;
                }
            }
    } else {
        float* C = out + (size_t)bp * Fc * Nn;
#pragma unroll
        for (int mt = 0; mt < 4; ++mt)
#pragma unroll
            for (int nt = 0; nt < 4; ++nt) {
#pragma unroll
                for (int h = 0; h < 2; ++h) {
                    int r = r_base + mt * 16 + h * 8;
                    int cc = c_base + nt * 8;
                    float bv = bias[r];
                    float t0 = acc[mt][nt][2 * h] + bv;
                    float t1 = acc[mt][nt][2 * h + 1] + bv;
                    t0 = t0 > 0.f ? t0 : 0.01f * t0;
                    t1 = t1 > 0.f ? t1 : 0.01f * t1;
                    *(float2*)(C + (size_t)r * Nn + cc) = make_float2(t0, t1);
                }
            }
    }
}

// ======================= launch ================================================
extern "C" void kernel_launch(void* const* d_in, const int* in_sizes, int n_in,
                              void* d_out, int out_size) {
    const float* x      = (const float*)d_in[0];
    const float* mixer  = (const float*)d_in[1];
    const float* weight = (const float*)d_in[2];
    const float* wb     = (const float*)d_in[3];
    const float* fw     = (const float*)d_in[4];
    const float* bias   = (const float*)d_in[5];
    const float* S      = (const float*)d_in[6];
    float* out = (float*)d_out;

    cudaFuncSetAttribute(mma_gemm, cudaFuncAttributeMaxDynamicSharedMemorySize, SMEM_GEMM);

    const int XT = Bc * Gc * Nn, FT = Pc * Fc * Kc * Gc;
    split_kernel<<<(XT + FT + 255) / 256, 256>>>(x, fw);        // 1
    pe_kernel<<<dim3(Nn / 256, NBP), 256>>>(x, mixer, weight, wb);  // 2
    aij_kernel<<<dim3(Nn, NBP), 256>>>(S);                      // 3

    dim3 gg(Nn / 128, 2, NBP);   // 8 x 2 x 32 = 512 CTAs
    for (int k = 1; k < Kc; ++k)                                // 4,5,6 (#4 profiled)
        mma_gemm<<<gg, 256, SMEM_GEMM>>>(bias, out, 0, k);
    mma_gemm<<<gg, 256, SMEM_GEMM>>>(bias, out, 1, 0);          // 7
}